// round 7
// baseline (speedup 1.0000x reference)
#include <cuda_runtime.h>

// out[i*2+0] = sum of edge_attr[e] for edges with edgeij_pair[0][e] == i
// out[i*2+1] = vertex_attr[i*2+1]

// Init: out row i = {0, y_i}. One coalesced float2 load + store per vertex.
__global__ void init_out_kernel(const float2* __restrict__ vattr,
                                float2* __restrict__ out, int n_vertices) {
    int i = blockIdx.x * blockDim.x + threadIdx.x;
    if (i < n_vertices) {
        float2 v = vattr[i];
        float2 o;
        o.x = 0.0f;
        o.y = v.y;
        out[i] = o;
    }
}

// Scatter: 2 edges/thread (empirically fastest config, R4). Launched with
// PDL (programmatic stream serialization): blocks start while init_out is
// still running, issue their edge loads immediately (disjoint buffers),
// then griddepcontrol.wait before the first atomic touches `out`.
__global__ void __launch_bounds__(256) scatter_add_kernel(
        const int2* __restrict__ idx2,
        const float2* __restrict__ val2,
        float* __restrict__ out, int n_pairs) {
    int t = blockIdx.x * blockDim.x + threadIdx.x;
    int2   vi;
    float2 va;
    bool active = (t < n_pairs);
    if (active) {
        vi = idx2[t];
        va = val2[t];
    }
    // Wait for init_out_kernel completion (implicit trigger at its exit);
    // guarantees its stores to `out` are visible before our atomics.
    asm volatile("griddepcontrol.wait;" ::: "memory");
    if (active) {
        atomicAdd(out + 2 * vi.x, va.x);
        atomicAdd(out + 2 * vi.y, va.y);
    }
}

__global__ void scatter_tail_kernel(const int* __restrict__ idx,
                                    const float* __restrict__ val,
                                    float* __restrict__ out,
                                    int start, int n_edges) {
    int e = start + blockIdx.x * blockDim.x + threadIdx.x;
    if (e < n_edges)
        atomicAdd(out + 2 * idx[e], val[e]);
}

extern "C" void kernel_launch(void* const* d_in, const int* in_sizes, int n_in,
                              void* d_out, int out_size) {
    // metadata order: vertex_attr [N,2] f32, edgeij_pair [2,E] i32,
    //                 edge_attr [E,1] f32, g [1,1] f32, batch [N] i32
    const float* vattr = (const float*)d_in[0];
    const int*   eij   = (const int*)d_in[1];
    const float* eattr = (const float*)d_in[2];
    float* out = (float*)d_out;

    int n_vertices = in_sizes[0] / 2;
    int n_edges    = in_sizes[2];
    const int* src_idx = eij; // row 0 of [2, E]

    const int threads = 256;

    // 1) init (primary)
    {
        int blocks = (n_vertices + threads - 1) / threads;
        init_out_kernel<<<blocks, threads>>>(
            (const float2*)vattr, (float2*)out, n_vertices);
    }

    // 2) scatter (secondary, PDL-overlapped with init)
    {
        int n_pairs = n_edges / 2;
        int blocks = (n_pairs + threads - 1) / threads;
        if (blocks > 0) {
            cudaLaunchConfig_t cfg = {};
            cfg.gridDim = dim3(blocks, 1, 1);
            cfg.blockDim = dim3(threads, 1, 1);
            cfg.dynamicSmemBytes = 0;
            cfg.stream = 0;
            cudaLaunchAttribute attrs[1];
            attrs[0].id = cudaLaunchAttributeProgrammaticStreamSerialization;
            attrs[0].val.programmaticStreamSerializationAllowed = 1;
            cfg.attrs = attrs;
            cfg.numAttrs = 1;
            cudaLaunchKernelEx(&cfg, scatter_add_kernel,
                               (const int2*)src_idx, (const float2*)eattr,
                               out, n_pairs);
        }
        int done = n_pairs * 2;
        if (done < n_edges)
            scatter_tail_kernel<<<1, 32>>>(src_idx, eattr, out,
                                           done, n_edges);
    }
}